// round 11
// baseline (speedup 1.0000x reference)
#include <cuda_runtime.h>
#include <cstdint>
#include <cstddef>

#define BDIM 8192
#define CDIM 4096
#define NQKV 12288

__device__ __align__(1024) float g_x [(size_t)BDIM * CDIM];
__device__ __align__(1024) float g_wq[(size_t)NQKV * CDIM];
__device__ __align__(1024) float g_wp[(size_t)CDIM * CDIM];
__device__ __align__(1024) float g_qkv[(size_t)BDIM * NQKV];
__device__ __align__(1024) float g_attn[(size_t)BDIM * CDIM];

__device__ __forceinline__ uint32_t smem_u32(const void* p) {
    uint32_t a;
    asm("{ .reg .u64 t; cvta.to.shared.u64 t, %1; cvt.u32.u64 %0, t; }" : "=r"(a) : "l"(p));
    return a;
}
__device__ __forceinline__ float rna(float x) {
    uint32_t u; asm("cvt.rna.tf32.f32 %0, %1;" : "=r"(u) : "f"(x));
    return __uint_as_float(u);
}
__device__ __forceinline__ void mma8(float* c, const uint32_t* a, const uint32_t* b) {
    asm volatile("mma.sync.aligned.m16n8k8.row.col.f32.tf32.tf32.f32 "
        "{%0,%1,%2,%3}, {%4,%5,%6,%7}, {%8,%9}, {%0,%1,%2,%3};"
        : "+f"(c[0]), "+f"(c[1]), "+f"(c[2]), "+f"(c[3])
        : "r"(a[0]), "r"(a[1]), "r"(a[2]), "r"(a[3]), "r"(b[0]), "r"(b[1]));
}
__device__ __forceinline__ void cpasync16(uint32_t dst, const float* src) {
    asm volatile("cp.async.cg.shared.global [%0], [%1], 16;" :: "r"(dst), "l"(src));
}
#define CP_COMMIT asm volatile("cp.async.commit_group;" ::: "memory")
#define CP_WAIT2  asm volatile("cp.async.wait_group 2;" ::: "memory")

// tf32 pre-round + k-permute (within each 8-group store order [0,4,1,5,2,6,3,7])
__global__ void __launch_bounds__(256) cvt_k(float* __restrict__ d, const float* __restrict__ s, int n8) {
    int i = blockIdx.x * blockDim.x + threadIdx.x, st = gridDim.x * blockDim.x;
    const float4* s4 = (const float4*)s;
    float4* d4 = (float4*)d;
    for (; i < n8; i += st) {
        float4 v0 = s4[2 * i], v1 = s4[2 * i + 1];
        float4 o0, o1;
        o0.x = rna(v0.x); o0.y = rna(v1.x); o0.z = rna(v0.y); o0.w = rna(v1.y);
        o1.x = rna(v0.z); o1.y = rna(v1.z); o1.z = rna(v0.w); o1.w = rna(v1.w);
        d4[2 * i] = o0; d4[2 * i + 1] = o1;
    }
}

// C[m,n] = sum_k A[m,k]*B[n,k] (+bias[n]); A,B K-major k-PERMUTED tf32. K=4096.
// 128x128 tile, 128 thr, 4 warps of 64x64, BK=16, 4-stage cp.async,
// k-loop unrolled by 4 so stage index is compile-time (imm-offset smem addressing).
#define RSTR 24
#define SSTG (128 * RSTR * 2)     // floats per stage
#define SSTGB (SSTG * 4)          // bytes per stage
#define NSTG 4
__global__ void __launch_bounds__(128, 2) gemm_tf32(
    const float* __restrict__ A, const float* __restrict__ B,
    float* __restrict__ C, const float* __restrict__ bias, int ntot)
{
    extern __shared__ __align__(16) float smf[];
    const int tid = threadIdx.x, lane = tid & 31, wid = tid >> 5;
    const int gid = lane >> 2, tig = lane & 3;
    const int wm = wid & 1, wn = wid >> 1;      // 2x2 warp grid, 64x64 each

    const int tn = gridDim.x, tm = gridDim.y;
    const int lin = blockIdx.y * tn + blockIdx.x;
    const int GN = 8;
    const int stripe = lin / (tm * GN), rem = lin - stripe * (tm * GN);
    const int width = min(GN, tn - stripe * GN);
    const int n0 = (stripe * GN + rem % width) * 128;
    const int m0 = (rem / width) * 128;

    float acc[4][8][4] = {};
    const uint32_t sb = smem_u32(smf);

    // loop-invariant bases: r = tid>>2 + j*32 (j*32*4096 is a constant offset),
    // c = tid&3 — so one gmem pointer + imm deltas, one smem base + imm deltas.
    const float* Ap = A + (size_t)(m0 + (tid >> 2)) * 4096 + (tid & 3) * 4;
    const float* Bp = B + (size_t)(n0 + (tid >> 2)) * 4096 + (tid & 3) * 4;
    const uint32_t sa_dst = sb + ((tid >> 2) * RSTR + (tid & 3) * 4) * 4;
    const uint32_t sb_dst = sa_dst + 128 * RSTR * 4;

    auto issue = [&](int s, int kt) {
        const float* Ak = Ap + kt * 16;
        const float* Bk = Bp + kt * 16;
        uint32_t das = sa_dst + s * SSTGB;
        uint32_t dbs = sb_dst + s * SSTGB;
        #pragma unroll
        for (int j = 0; j < 4; j++) {
            cpasync16(das + j * 32 * RSTR * 4, Ak + (size_t)j * 32 * 4096);
            cpasync16(dbs + j * 32 * RSTR * 4, Bk + (size_t)j * 32 * 4096);
        }
    };

    issue(0, 0); CP_COMMIT;
    issue(1, 1); CP_COMMIT;
    issue(2, 2); CP_COMMIT;

    const float* As_base = smf + (wm * 64 + gid) * RSTR;
    const float* Bs_base = smf + 128 * RSTR + (wn * 64 + gid) * RSTR;

    #pragma unroll 1
    for (int ktb = 0; ktb < 256; ktb += 4) {
        #pragma unroll
        for (int u = 0; u < 4; u++) {          // u == stage index (compile-time)
            CP_WAIT2;
            __syncthreads();
            if (ktb + u + 3 < 256) issue((u + 3) & 3, ktb + u + 3);
            CP_COMMIT;

            const float* As = As_base + u * SSTG;   // imm-folded stage offset
            const float* Bs = Bs_base + u * SSTG;
            #pragma unroll
            for (int ks = 0; ks < 2; ks++) {
                const int k8 = ks * 8 + tig * 2;
                uint32_t a[4][4], bf[8][2];
                #pragma unroll
                for (int mt = 0; mt < 4; mt++) {
                    float2 lo = *(const float2*)(As + mt * 16 * RSTR + k8);
                    float2 hi = *(const float2*)(As + (mt * 16 + 8) * RSTR + k8);
                    a[mt][0] = __float_as_uint(lo.x); a[mt][1] = __float_as_uint(hi.x);
                    a[mt][2] = __float_as_uint(lo.y); a[mt][3] = __float_as_uint(hi.y);
                }
                #pragma unroll
                for (int nt = 0; nt < 8; nt++) {
                    float2 bb = *(const float2*)(Bs + nt * 8 * RSTR + k8);
                    bf[nt][0] = __float_as_uint(bb.x); bf[nt][1] = __float_as_uint(bb.y);
                }
                #pragma unroll
                for (int mt = 0; mt < 4; mt++)
                    #pragma unroll
                    for (int nt = 0; nt < 8; nt++)
                        mma8(acc[mt][nt], a[mt], bf[nt]);
            }
        }
    }

    #pragma unroll
    for (int mt = 0; mt < 4; mt++) {
        #pragma unroll
        for (int nt = 0; nt < 8; nt++) {
            int row = m0 + wm * 64 + mt * 16 + gid;
            int col = n0 + wn * 64 + nt * 8 + tig * 2;
            float b0 = 0.f, b1 = 0.f;
            if (bias) { b0 = bias[col]; b1 = bias[col + 1]; }
            *(float2*)(C + (size_t)row * ntot + col) =
                make_float2(acc[mt][nt][0] + b0, acc[mt][nt][1] + b1);
            *(float2*)(C + (size_t)(row + 8) * ntot + col) =
                make_float2(acc[mt][nt][2] + b0, acc[mt][nt][3] + b1);
        }
    }
}

// per-token 32x32 head-mixing attention; out col = d*32+h, tf32-rounded,
// stored k-PERMUTED (feeds gemm2 A); permute acts on lane (= h) bits.
#define RS 132
__global__ void __launch_bounds__(128) attn_kernel(
    const float* __restrict__ qkv, float* __restrict__ attn)
{
    extern __shared__ float sm[];
    const int b = blockIdx.x, t = threadIdx.x, w = t >> 5, lane = t & 31;

    const float4* src4 = (const float4*)(qkv + (size_t)b * NQKV);
    for (int i = t; i < 3072; i += 128) {
        int mat = i >> 10, rm = i & 1023;
        *(float4*)(sm + mat * (32 * RS) + (rm >> 5) * RS + (rm & 31) * 4) = src4[i];
    }
    __syncthreads();

    float* sq = sm;
    float* sk = sm + 32 * RS;
    float* sv = sm + 64 * RS;
    float* ss = sm + 96 * RS;
    const float scale = 0.08838834764831845f;

    {
        float a8[8] = {};
        #pragma unroll
        for (int ch = 0; ch < 4; ch++) {
            float4 q[8];
            #pragma unroll
            for (int j = 0; j < 8; j++)
                q[j] = *(const float4*)(sq + lane * RS + ch * 32 + j * 4);
            #pragma unroll
            for (int g0 = 0; g0 < 8; g0++) {
                const float* kr = sk + (w * 8 + g0) * RS + ch * 32;
                #pragma unroll
                for (int j = 0; j < 8; j++) {
                    float4 k4 = *(const float4*)(kr + j * 4);
                    a8[g0] += q[j].x * k4.x + q[j].y * k4.y + q[j].z * k4.z + q[j].w * k4.w;
                }
            }
        }
        #pragma unroll
        for (int g0 = 0; g0 < 8; g0++) ss[lane * 33 + w * 8 + g0] = a8[g0] * scale;
    }
    __syncthreads();

    if (w == 0) {
        float mx = -1e30f;
        #pragma unroll
        for (int g = 0; g < 32; g++) mx = fmaxf(mx, ss[lane * 33 + g]);
        float sum = 0.f;
        #pragma unroll
        for (int g = 0; g < 32; g++) {
            float e = __expf(ss[lane * 33 + g] - mx);
            ss[lane * 33 + g] = e; sum += e;
        }
        float inv = 1.f / sum;
        #pragma unroll
        for (int g = 0; g < 32; g++) ss[lane * 33 + g] *= inv;
    }
    __syncthreads();

    {
        float4 acc[8];
        #pragma unroll
        for (int j = 0; j < 8; j++) acc[j] = make_float4(0.f, 0.f, 0.f, 0.f);
        #pragma unroll
        for (int g = 0; g < 32; g++) {
            float a = ss[lane * 33 + g];
            const float* vr = sv + g * RS + w * 32;
            #pragma unroll
            for (int j = 0; j < 8; j++) {
                float4 v4 = *(const float4*)(vr + j * 4);
                acc[j].x += a * v4.x; acc[j].y += a * v4.y;
                acc[j].z += a * v4.z; acc[j].w += a * v4.w;
            }
        }
        const int plane = (lane & 24) | ((lane & 3) << 1) | ((lane >> 2) & 1);
        float* dst = attn + (size_t)b * CDIM;
        #pragma unroll
        for (int j = 0; j < 8; j++) {
            int d0 = w * 32 + j * 4;
            dst[(d0 + 0) * 32 + plane] = rna(acc[j].x);
            dst[(d0 + 1) * 32 + plane] = rna(acc[j].y);
            dst[(d0 + 2) * 32 + plane] = rna(acc[j].z);
            dst[(d0 + 3) * 32 + plane] = rna(acc[j].w);
        }
    }
}

extern "C" void kernel_launch(void* const* d_in, const int* in_sizes, int n_in,
                              void* d_out, int out_size)
{
    const float* x  = (const float*)d_in[0];
    const float* wq = (const float*)d_in[1];
    const float* wp = (const float*)d_in[2];
    const float* bp = (const float*)d_in[3];
    float* out = (float*)d_out;

    float *gx, *gwq, *gwp, *qkv, *attn;
    cudaGetSymbolAddress((void**)&gx, g_x);
    cudaGetSymbolAddress((void**)&gwq, g_wq);
    cudaGetSymbolAddress((void**)&gwp, g_wp);
    cudaGetSymbolAddress((void**)&qkv, g_qkv);
    cudaGetSymbolAddress((void**)&attn, g_attn);

    cudaFuncSetAttribute(gemm_tf32, cudaFuncAttributeMaxDynamicSharedMemorySize, NSTG * SSTGB);
    cudaFuncSetAttribute(attn_kernel, cudaFuncAttributeMaxDynamicSharedMemorySize, 55296);

    cvt_k<<<512, 256>>>(gx, x, (int)((size_t)BDIM * CDIM / 8));
    cvt_k<<<512, 256>>>(gwq, wq, (int)((size_t)NQKV * CDIM / 8));
    cvt_k<<<512, 256>>>(gwp, wp, (int)((size_t)CDIM * CDIM / 8));
    gemm_tf32<<<dim3(96, 64), 128, NSTG * SSTGB>>>(gx, gwq, qkv, nullptr, NQKV);
    attn_kernel<<<BDIM, 128, 55296>>>(qkv, attn);
    gemm_tf32<<<dim3(32, 64), 128, NSTG * SSTGB>>>(attn, gwp, out, bp, CDIM);
}

// round 12
// speedup vs baseline: 1.0585x; 1.0585x over previous
#include <cuda_runtime.h>
#include <cstdint>
#include <cstddef>

#define BDIM 8192
#define CDIM 4096
#define NQKV 12288

__device__ __align__(1024) float g_x [(size_t)BDIM * CDIM];
__device__ __align__(1024) float g_wq[(size_t)NQKV * CDIM];
__device__ __align__(1024) float g_wp[(size_t)CDIM * CDIM];
__device__ __align__(1024) float g_qkv[(size_t)BDIM * NQKV];
__device__ __align__(1024) float g_attn[(size_t)BDIM * CDIM];

__device__ __forceinline__ uint32_t smem_u32(const void* p) {
    uint32_t a;
    asm("{ .reg .u64 t; cvta.to.shared.u64 t, %1; cvt.u32.u64 %0, t; }" : "=r"(a) : "l"(p));
    return a;
}
__device__ __forceinline__ float rna(float x) {
    uint32_t u; asm("cvt.rna.tf32.f32 %0, %1;" : "=r"(u) : "f"(x));
    return __uint_as_float(u);
}
__device__ __forceinline__ void mma8(float* c, const uint32_t* a, const uint32_t* b) {
    asm volatile("mma.sync.aligned.m16n8k8.row.col.f32.tf32.tf32.f32 "
        "{%0,%1,%2,%3}, {%4,%5,%6,%7}, {%8,%9}, {%0,%1,%2,%3};"
        : "+f"(c[0]), "+f"(c[1]), "+f"(c[2]), "+f"(c[3])
        : "r"(a[0]), "r"(a[1]), "r"(a[2]), "r"(a[3]), "r"(b[0]), "r"(b[1]));
}
__device__ __forceinline__ void cpasync16(uint32_t dst, const float* src) {
    asm volatile("cp.async.cg.shared.global [%0], [%1], 16;" :: "r"(dst), "l"(src));
}
#define CP_COMMIT asm volatile("cp.async.commit_group;" ::: "memory")
#define CP_WAIT2  asm volatile("cp.async.wait_group 2;" ::: "memory")

// tf32 pre-round + k-permute (within each 8-group store order [0,4,1,5,2,6,3,7])
__global__ void __launch_bounds__(256) cvt_k(float* __restrict__ d, const float* __restrict__ s, int n8) {
    int i = blockIdx.x * blockDim.x + threadIdx.x, st = gridDim.x * blockDim.x;
    const float4* s4 = (const float4*)s;
    float4* d4 = (float4*)d;
    for (; i < n8; i += st) {
        float4 v0 = s4[2 * i], v1 = s4[2 * i + 1];
        float4 o0, o1;
        o0.x = rna(v0.x); o0.y = rna(v1.x); o0.z = rna(v0.y); o0.w = rna(v1.y);
        o1.x = rna(v0.z); o1.y = rna(v1.z); o1.z = rna(v0.w); o1.w = rna(v1.w);
        d4[2 * i] = o0; d4[2 * i + 1] = o1;
    }
}

// C[m,n] = sum_k A[m,k]*B[n,k] (+bias[n]); A,B K-major k-PERMUTED tf32. K=4096.
// 128x128 tile, 128 thr, 4 warps of 64x64, BK=16, 4-stage cp.async.
// Both ks-halves' fragments hoisted ahead of all 64 MMAs (intra-warp latency hiding).
#define RSTR 24
#define SSTG (128 * RSTR * 2)
#define NSTG 4
__global__ void __launch_bounds__(128, 2) gemm_tf32(
    const float* __restrict__ A, const float* __restrict__ B,
    float* __restrict__ C, const float* __restrict__ bias, int ntot)
{
    extern __shared__ __align__(16) float smf[];
    const int tid = threadIdx.x, lane = tid & 31, wid = tid >> 5;
    const int gid = lane >> 2, tig = lane & 3;
    const int wm = wid & 1, wn = wid >> 1;       // 2x2 warp grid, 64x64 each

    const int tn = gridDim.x, tm = gridDim.y;
    const int lin = blockIdx.y * tn + blockIdx.x;
    const int GN = 8;
    const int stripe = lin / (tm * GN), rem = lin - stripe * (tm * GN);
    const int width = min(GN, tn - stripe * GN);
    const int n0 = (stripe * GN + rem % width) * 128;
    const int m0 = (rem / width) * 128;

    float acc[4][8][4] = {};
    const uint32_t sb = smem_u32(smf);

    auto issue = [&](int sidx, int kt) {
        uint32_t da = sb + sidx * SSTG * 4, db = da + 128 * RSTR * 4;
        #pragma unroll
        for (int i = tid; i < 512; i += 128) {
            int r = i >> 2, c = i & 3;
            cpasync16(da + (r * RSTR + c * 4) * 4, A + (size_t)(m0 + r) * 4096 + kt * 16 + c * 4);
            cpasync16(db + (r * RSTR + c * 4) * 4, B + (size_t)(n0 + r) * 4096 + kt * 16 + c * 4);
        }
    };

    issue(0, 0); CP_COMMIT;
    issue(1, 1); CP_COMMIT;
    issue(2, 2); CP_COMMIT;

    int buf = 0;
    #pragma unroll 1
    for (int kt = 0; kt < 256; kt++) {
        CP_WAIT2;
        __syncthreads();
        int nb = buf + 3; if (nb >= NSTG) nb -= NSTG;
        if (kt + 3 < 256) issue(nb, kt + 3);
        CP_COMMIT;

        const float* As = smf + buf * SSTG + (wm * 64 + gid) * RSTR;
        const float* Bs = smf + buf * SSTG + 128 * RSTR + (wn * 64 + gid) * RSTR;

        // hoist BOTH halves' fragment loads (all independent LDS.64)
        uint32_t a[2][4][4], bf[2][8][2];
        #pragma unroll
        for (int ks = 0; ks < 2; ks++) {
            const int k8 = ks * 8 + tig * 2;
            #pragma unroll
            for (int mt = 0; mt < 4; mt++) {
                float2 lo = *(const float2*)(As + mt * 16 * RSTR + k8);
                float2 hi = *(const float2*)(As + (mt * 16 + 8) * RSTR + k8);
                a[ks][mt][0] = __float_as_uint(lo.x); a[ks][mt][1] = __float_as_uint(hi.x);
                a[ks][mt][2] = __float_as_uint(lo.y); a[ks][mt][3] = __float_as_uint(hi.y);
            }
            #pragma unroll
            for (int nt = 0; nt < 8; nt++) {
                float2 bb = *(const float2*)(Bs + nt * 8 * RSTR + k8);
                bf[ks][nt][0] = __float_as_uint(bb.x); bf[ks][nt][1] = __float_as_uint(bb.y);
            }
        }
        #pragma unroll
        for (int ks = 0; ks < 2; ks++)
            #pragma unroll
            for (int mt = 0; mt < 4; mt++)
                #pragma unroll
                for (int nt = 0; nt < 8; nt++)
                    mma8(acc[mt][nt], a[ks][mt], bf[ks][nt]);

        if (++buf == NSTG) buf = 0;
    }

    #pragma unroll
    for (int mt = 0; mt < 4; mt++) {
        #pragma unroll
        for (int nt = 0; nt < 8; nt++) {
            int row = m0 + wm * 64 + mt * 16 + gid;
            int col = n0 + wn * 64 + nt * 8 + tig * 2;
            float b0 = 0.f, b1 = 0.f;
            if (bias) { b0 = bias[col]; b1 = bias[col + 1]; }
            *(float2*)(C + (size_t)row * ntot + col) =
                make_float2(acc[mt][nt][0] + b0, acc[mt][nt][1] + b1);
            *(float2*)(C + (size_t)(row + 8) * ntot + col) =
                make_float2(acc[mt][nt][2] + b0, acc[mt][nt][3] + b1);
        }
    }
}

// per-token 32x32 head-mixing attention; out col = d*32+h, tf32-rounded,
// stored k-PERMUTED (feeds gemm2 A); permute acts on lane (= h) bits.
#define RS 132
__global__ void __launch_bounds__(128) attn_kernel(
    const float* __restrict__ qkv, float* __restrict__ attn)
{
    extern __shared__ float sm[];
    const int b = blockIdx.x, t = threadIdx.x, w = t >> 5, lane = t & 31;

    const float4* src4 = (const float4*)(qkv + (size_t)b * NQKV);
    for (int i = t; i < 3072; i += 128) {
        int mat = i >> 10, rm = i & 1023;
        *(float4*)(sm + mat * (32 * RS) + (rm >> 5) * RS + (rm & 31) * 4) = src4[i];
    }
    __syncthreads();

    float* sq = sm;
    float* sk = sm + 32 * RS;
    float* sv = sm + 64 * RS;
    float* ss = sm + 96 * RS;
    const float scale = 0.08838834764831845f;

    {
        float a8[8] = {};
        #pragma unroll
        for (int ch = 0; ch < 4; ch++) {
            float4 q[8];
            #pragma unroll
            for (int j = 0; j < 8; j++)
                q[j] = *(const float4*)(sq + lane * RS + ch * 32 + j * 4);
            #pragma unroll
            for (int g0 = 0; g0 < 8; g0++) {
                const float* kr = sk + (w * 8 + g0) * RS + ch * 32;
                #pragma unroll
                for (int j = 0; j < 8; j++) {
                    float4 k4 = *(const float4*)(kr + j * 4);
                    a8[g0] += q[j].x * k4.x + q[j].y * k4.y + q[j].z * k4.z + q[j].w * k4.w;
                }
            }
        }
        #pragma unroll
        for (int g0 = 0; g0 < 8; g0++) ss[lane * 33 + w * 8 + g0] = a8[g0] * scale;
    }
    __syncthreads();

    if (w == 0) {
        float mx = -1e30f;
        #pragma unroll
        for (int g = 0; g < 32; g++) mx = fmaxf(mx, ss[lane * 33 + g]);
        float sum = 0.f;
        #pragma unroll
        for (int g = 0; g < 32; g++) {
            float e = __expf(ss[lane * 33 + g] - mx);
            ss[lane * 33 + g] = e; sum += e;
        }
        float inv = 1.f / sum;
        #pragma unroll
        for (int g = 0; g < 32; g++) ss[lane * 33 + g] *= inv;
    }
    __syncthreads();

    {
        float4 acc[8];
        #pragma unroll
        for (int j = 0; j < 8; j++) acc[j] = make_float4(0.f, 0.f, 0.f, 0.f);
        #pragma unroll
        for (int g = 0; g < 32; g++) {
            float a = ss[lane * 33 + g];
            const float* vr = sv + g * RS + w * 32;
            #pragma unroll
            for (int j = 0; j < 8; j++) {
                float4 v4 = *(const float4*)(vr + j * 4);
                acc[j].x += a * v4.x; acc[j].y += a * v4.y;
                acc[j].z += a * v4.z; acc[j].w += a * v4.w;
            }
        }
        const int plane = (lane & 24) | ((lane & 3) << 1) | ((lane >> 2) & 1);
        float* dst = attn + (size_t)b * CDIM;
        #pragma unroll
        for (int j = 0; j < 8; j++) {
            int d0 = w * 32 + j * 4;
            dst[(d0 + 0) * 32 + plane] = rna(acc[j].x);
            dst[(d0 + 1) * 32 + plane] = rna(acc[j].y);
            dst[(d0 + 2) * 32 + plane] = rna(acc[j].z);
            dst[(d0 + 3) * 32 + plane] = rna(acc[j].w);
        }
    }
}

extern "C" void kernel_launch(void* const* d_in, const int* in_sizes, int n_in,
                              void* d_out, int out_size)
{
    const float* x  = (const float*)d_in[0];
    const float* wq = (const float*)d_in[1];
    const float* wp = (const float*)d_in[2];
    const float* bp = (const float*)d_in[3];
    float* out = (float*)d_out;

    float *gx, *gwq, *gwp, *qkv, *attn;
    cudaGetSymbolAddress((void**)&gx, g_x);
    cudaGetSymbolAddress((void**)&gwq, g_wq);
    cudaGetSymbolAddress((void**)&gwp, g_wp);
    cudaGetSymbolAddress((void**)&qkv, g_qkv);
    cudaGetSymbolAddress((void**)&attn, g_attn);

    cudaFuncSetAttribute(gemm_tf32, cudaFuncAttributeMaxDynamicSharedMemorySize, NSTG * SSTG * 4);
    cudaFuncSetAttribute(attn_kernel, cudaFuncAttributeMaxDynamicSharedMemorySize, 55296);

    cvt_k<<<512, 256>>>(gx, x, (int)((size_t)BDIM * CDIM / 8));
    cvt_k<<<512, 256>>>(gwq, wq, (int)((size_t)NQKV * CDIM / 8));
    cvt_k<<<512, 256>>>(gwp, wp, (int)((size_t)CDIM * CDIM / 8));
    gemm_tf32<<<dim3(96, 64), 128, NSTG * SSTG * 4>>>(gx, gwq, qkv, nullptr, NQKV);
    attn_kernel<<<BDIM, 128, 55296>>>(qkv, attn);
    gemm_tf32<<<dim3(32, 64), 128, NSTG * SSTG * 4>>>(attn, gwp, out, bp, CDIM);
}

// round 13
// speedup vs baseline: 1.1868x; 1.1212x over previous
#include <cuda_runtime.h>
#include <cstdint>
#include <cstddef>

#define BDIM 8192
#define CDIM 4096
#define NQKV 12288

__device__ __align__(1024) float g_x [(size_t)BDIM * CDIM];
__device__ __align__(1024) float g_wq[(size_t)NQKV * CDIM];
__device__ __align__(1024) float g_wp[(size_t)CDIM * CDIM];
__device__ __align__(1024) float g_qkv[(size_t)BDIM * NQKV];
__device__ __align__(1024) float g_attn[(size_t)BDIM * CDIM];

__device__ __forceinline__ float rna(float x) {
    uint32_t u; asm("cvt.rna.tf32.f32 %0, %1;" : "=r"(u) : "f"(x));
    return __uint_as_float(u);
}
__device__ __forceinline__ uint32_t smem_u32(const void* p) {
    uint32_t a;
    asm("{ .reg .u64 t; cvta.to.shared.u64 t, %1; cvt.u32.u64 %0, t; }" : "=r"(a) : "l"(p));
    return a;
}
__device__ __forceinline__ void mma8(float* c, const uint32_t* a, const uint32_t* b) {
    asm volatile("mma.sync.aligned.m16n8k8.row.col.f32.tf32.tf32.f32 "
        "{%0,%1,%2,%3}, {%4,%5,%6,%7}, {%8,%9}, {%0,%1,%2,%3};"
        : "+f"(c[0]), "+f"(c[1]), "+f"(c[2]), "+f"(c[3])
        : "r"(a[0]), "r"(a[1]), "r"(a[2]), "r"(a[3]), "r"(b[0]), "r"(b[1]));
}
__device__ __forceinline__ void cpasync16(uint32_t dst, const float* src) {
    asm volatile("cp.async.cg.shared.global [%0], [%1], 16;" :: "r"(dst), "l"(src));
}
#define CP_COMMIT asm volatile("cp.async.commit_group;" ::: "memory")
#define CP_WAIT1  asm volatile("cp.async.wait_group 1;" ::: "memory")
#define CP_WAIT2  asm volatile("cp.async.wait_group 2;" ::: "memory")

// tf32 pre-round + k-permute (within each 8-group store order [0,4,1,5,2,6,3,7])
__global__ void __launch_bounds__(256) cvt_k(float* __restrict__ d, const float* __restrict__ s, int n8) {
    int i = blockIdx.x * blockDim.x + threadIdx.x, st = gridDim.x * blockDim.x;
    const float4* s4 = (const float4*)s;
    float4* d4 = (float4*)d;
    for (; i < n8; i += st) {
        float4 v0 = s4[2 * i], v1 = s4[2 * i + 1];
        float4 o0, o1;
        o0.x = rna(v0.x); o0.y = rna(v1.x); o0.z = rna(v0.y); o0.w = rna(v1.y);
        o1.x = rna(v0.z); o1.y = rna(v1.z); o1.z = rna(v0.w); o1.w = rna(v1.w);
        d4[2 * i] = o0; d4[2 * i + 1] = o1;
    }
}

#define RSTR 24
#define SSTG (128 * RSTR * 2)
#define NSTG 4

#define LOADF(Asp, Bsp, K8, aa, bb) do {                                        \
    _Pragma("unroll") for (int mt = 0; mt < 4; mt++) {                          \
        float2 lo = *(const float2*)((Asp) + mt * 16 * RSTR + (K8));            \
        float2 hi = *(const float2*)((Asp) + (mt * 16 + 8) * RSTR + (K8));      \
        aa[mt][0] = __float_as_uint(lo.x); aa[mt][1] = __float_as_uint(hi.x);   \
        aa[mt][2] = __float_as_uint(lo.y); aa[mt][3] = __float_as_uint(hi.y);   \
    }                                                                           \
    _Pragma("unroll") for (int nt = 0; nt < 8; nt++) {                          \
        float2 b2 = *(const float2*)((Bsp) + nt * 8 * RSTR + (K8));             \
        bb[nt][0] = __float_as_uint(b2.x); bb[nt][1] = __float_as_uint(b2.y);   \
    }                                                                           \
} while (0)

#define MMAS(aa, bb) do {                                                       \
    _Pragma("unroll") for (int mt = 0; mt < 4; mt++)                            \
        _Pragma("unroll") for (int nt = 0; nt < 8; nt++)                        \
            mma8(acc[mt][nt], aa[mt], bb[nt]);                                  \
} while (0)

// C[m,n] = sum_k A[m,k]*B[n,k] (+bias[n]); A,B K-major k-PERMUTED tf32. K=4096.
// 128x128 tile, 4 warps of 64x64, BK=16, 4-stage cp.async, cross-barrier
// register double-buffering: frags for tile kt+1 loaded while tile kt computes.
__global__ void __launch_bounds__(128, 2) gemm_tf32(
    const float* __restrict__ A, const float* __restrict__ B,
    float* __restrict__ C, const float* __restrict__ bias, int ntot)
{
    extern __shared__ __align__(16) float smf[];
    const int tid = threadIdx.x, lane = tid & 31, wid = tid >> 5;
    const int gid = lane >> 2, tig = lane & 3;
    const int wm = wid & 1, wn = wid >> 1;       // 2x2 warp grid, 64x64 each

    const int tn = gridDim.x, tm = gridDim.y;
    const int lin = blockIdx.y * tn + blockIdx.x;
    const int GN = 8;
    const int stripe = lin / (tm * GN), rem = lin - stripe * (tm * GN);
    const int width = min(GN, tn - stripe * GN);
    const int n0 = (stripe * GN + rem % width) * 128;
    const int m0 = (rem / width) * 128;

    float acc[4][8][4] = {};
    const uint32_t sb = smem_u32(smf);

    auto issue = [&](int sidx, int kt) {
        uint32_t da = sb + sidx * SSTG * 4, db = da + 128 * RSTR * 4;
        #pragma unroll
        for (int i = tid; i < 512; i += 128) {
            int r = i >> 2, c = i & 3;
            cpasync16(da + (r * RSTR + c * 4) * 4, A + (size_t)(m0 + r) * 4096 + kt * 16 + c * 4);
            cpasync16(db + (r * RSTR + c * 4) * 4, B + (size_t)(n0 + r) * 4096 + kt * 16 + c * 4);
        }
    };

    issue(0, 0); CP_COMMIT;
    issue(1, 1); CP_COMMIT;
    issue(2, 2); CP_COMMIT;

    const int aoff = (wm * 64 + gid) * RSTR;
    const int boff = 128 * RSTR + (wn * 64 + gid) * RSTR;
    const int k80 = tig * 2, k81 = 8 + tig * 2;

    uint32_t a0[4][4], b0[8][2], a1[4][4], b1[8][2];

    // prologue: stage 0 visible, preload its first half
    CP_WAIT2;
    __syncthreads();
    LOADF(smf + aoff, smf + boff, k80, a0, b0);

    int buf = 0;
    #pragma unroll 1
    for (int kt = 0; kt < 256; kt++) {
        CP_WAIT1;              // stages kt AND kt+1 complete
        __syncthreads();       // ... and CTA-visible
        int nb = buf + 3; if (nb >= NSTG) nb -= NSTG;
        if (kt + 3 < 256) issue(nb, kt + 3);
        CP_COMMIT;

        const float* As = smf + buf * SSTG;
        int buf1 = buf + 1; if (buf1 >= NSTG) buf1 -= NSTG;
        const float* As1 = smf + buf1 * SSTG;

        LOADF(As + aoff, As + boff, k81, a1, b1);       // this tile, half 1
        MMAS(a0, b0);                                   // half 0 (regs ready)
        if (kt + 1 < 256)
            LOADF(As1 + aoff, As1 + boff, k80, a0, b0); // NEXT tile, half 0
        MMAS(a1, b1);                                   // half 1

        buf = buf1;
    }

    #pragma unroll
    for (int mt = 0; mt < 4; mt++) {
        #pragma unroll
        for (int nt = 0; nt < 8; nt++) {
            int row = m0 + wm * 64 + mt * 16 + gid;
            int col = n0 + wn * 64 + nt * 8 + tig * 2;
            float b0v = 0.f, b1v = 0.f;
            if (bias) { b0v = bias[col]; b1v = bias[col + 1]; }
            *(float2*)(C + (size_t)row * ntot + col) =
                make_float2(acc[mt][nt][0] + b0v, acc[mt][nt][1] + b1v);
            *(float2*)(C + (size_t)(row + 8) * ntot + col) =
                make_float2(acc[mt][nt][2] + b0v, acc[mt][nt][3] + b1v);
        }
    }
}

// per-token 32x32 head-mixing attention; out col = d*32+h, tf32-rounded,
// stored k-PERMUTED (feeds gemm2 A); permute acts on lane (= h) bits.
#define RS 132
__global__ void __launch_bounds__(128) attn_kernel(
    const float* __restrict__ qkv, float* __restrict__ attn)
{
    extern __shared__ float sm[];
    const int b = blockIdx.x, t = threadIdx.x, w = t >> 5, lane = t & 31;

    const float4* src4 = (const float4*)(qkv + (size_t)b * NQKV);
    for (int i = t; i < 3072; i += 128) {
        int mat = i >> 10, rm = i & 1023;
        *(float4*)(sm + mat * (32 * RS) + (rm >> 5) * RS + (rm & 31) * 4) = src4[i];
    }
    __syncthreads();

    float* sq = sm;
    float* sk = sm + 32 * RS;
    float* sv = sm + 64 * RS;
    float* ss = sm + 96 * RS;
    const float scale = 0.08838834764831845f;

    {
        float a8[8] = {};
        #pragma unroll
        for (int ch = 0; ch < 4; ch++) {
            float4 q[8];
            #pragma unroll
            for (int j = 0; j < 8; j++)
                q[j] = *(const float4*)(sq + lane * RS + ch * 32 + j * 4);
            #pragma unroll
            for (int g0 = 0; g0 < 8; g0++) {
                const float* kr = sk + (w * 8 + g0) * RS + ch * 32;
                #pragma unroll
                for (int j = 0; j < 8; j++) {
                    float4 k4 = *(const float4*)(kr + j * 4);
                    a8[g0] += q[j].x * k4.x + q[j].y * k4.y + q[j].z * k4.z + q[j].w * k4.w;
                }
            }
        }
        #pragma unroll
        for (int g0 = 0; g0 < 8; g0++) ss[lane * 33 + w * 8 + g0] = a8[g0] * scale;
    }
    __syncthreads();

    if (w == 0) {
        float mx = -1e30f;
        #pragma unroll
        for (int g = 0; g < 32; g++) mx = fmaxf(mx, ss[lane * 33 + g]);
        float sum = 0.f;
        #pragma unroll
        for (int g = 0; g < 32; g++) {
            float e = __expf(ss[lane * 33 + g] - mx);
            ss[lane * 33 + g] = e; sum += e;
        }
        float inv = 1.f / sum;
        #pragma unroll
        for (int g = 0; g < 32; g++) ss[lane * 33 + g] *= inv;
    }
    __syncthreads();

    {
        float4 acc[8];
        #pragma unroll
        for (int j = 0; j < 8; j++) acc[j] = make_float4(0.f, 0.f, 0.f, 0.f);
        #pragma unroll
        for (int g = 0; g < 32; g++) {
            float a = ss[lane * 33 + g];
            const float* vr = sv + g * RS + w * 32;
            #pragma unroll
            for (int j = 0; j < 8; j++) {
                float4 v4 = *(const float4*)(vr + j * 4);
                acc[j].x += a * v4.x; acc[j].y += a * v4.y;
                acc[j].z += a * v4.z; acc[j].w += a * v4.w;
            }
        }
        const int plane = (lane & 24) | ((lane & 3) << 1) | ((lane >> 2) & 1);
        float* dst = attn + (size_t)b * CDIM;
        #pragma unroll
        for (int j = 0; j < 8; j++) {
            int d0 = w * 32 + j * 4;
            dst[(d0 + 0) * 32 + plane] = rna(acc[j].x);
            dst[(d0 + 1) * 32 + plane] = rna(acc[j].y);
            dst[(d0 + 2) * 32 + plane] = rna(acc[j].z);
            dst[(d0 + 3) * 32 + plane] = rna(acc[j].w);
        }
    }
}

extern "C" void kernel_launch(void* const* d_in, const int* in_sizes, int n_in,
                              void* d_out, int out_size)
{
    const float* x  = (const float*)d_in[0];
    const float* wq = (const float*)d_in[1];
    const float* wp = (const float*)d_in[2];
    const float* bp = (const float*)d_in[3];
    float* out = (float*)d_out;

    float *gx, *gwq, *gwp, *qkv, *attn;
    cudaGetSymbolAddress((void**)&gx, g_x);
    cudaGetSymbolAddress((void**)&gwq, g_wq);
    cudaGetSymbolAddress((void**)&gwp, g_wp);
    cudaGetSymbolAddress((void**)&qkv, g_qkv);
    cudaGetSymbolAddress((void**)&attn, g_attn);

    cudaFuncSetAttribute(gemm_tf32, cudaFuncAttributeMaxDynamicSharedMemorySize, NSTG * SSTG * 4);
    cudaFuncSetAttribute(attn_kernel, cudaFuncAttributeMaxDynamicSharedMemorySize, 55296);

    cvt_k<<<512, 256>>>(gx, x, (int)((size_t)BDIM * CDIM / 8));
    cvt_k<<<512, 256>>>(gwq, wq, (int)((size_t)NQKV * CDIM / 8));
    cvt_k<<<512, 256>>>(gwp, wp, (int)((size_t)CDIM * CDIM / 8));
    gemm_tf32<<<dim3(96, 64), 128, NSTG * SSTG * 4>>>(gx, gwq, qkv, nullptr, NQKV);
    attn_kernel<<<BDIM, 128, 55296>>>(qkv, attn);
    gemm_tf32<<<dim3(32, 64), 128, NSTG * SSTG * 4>>>(attn, gwp, out, bp, CDIM);
}

// round 17
// speedup vs baseline: 1.9108x; 1.6100x over previous
#include <cuda_runtime.h>
#include <cuda_fp16.h>
#include <cstdint>
#include <cstddef>

#define BDIM 8192
#define CDIM 4096
#define NQKV 12288

__device__ __align__(1024) __half h_x [(size_t)BDIM * CDIM];
__device__ __align__(1024) __half h_wq[(size_t)NQKV * CDIM];
__device__ __align__(1024) __half h_wp[(size_t)CDIM * CDIM];
__device__ __align__(1024) float  g_qkv[(size_t)BDIM * NQKV];
__device__ __align__(1024) __half h_attn[(size_t)BDIM * CDIM];

__device__ __forceinline__ uint32_t smem_u32(const void* p) {
    uint32_t a;
    asm("{ .reg .u64 t; cvta.to.shared.u64 t, %1; cvt.u32.u64 %0, t; }" : "=r"(a) : "l"(p));
    return a;
}
__device__ __forceinline__ void mma16(float* c, const uint32_t* a, const uint32_t* b) {
    asm volatile("mma.sync.aligned.m16n8k16.row.col.f32.f16.f16.f32 "
        "{%0,%1,%2,%3}, {%4,%5,%6,%7}, {%8,%9}, {%0,%1,%2,%3};"
        : "+f"(c[0]), "+f"(c[1]), "+f"(c[2]), "+f"(c[3])
        : "r"(a[0]), "r"(a[1]), "r"(a[2]), "r"(a[3]), "r"(b[0]), "r"(b[1]));
}
__device__ __forceinline__ void cpasync16(uint32_t dst, const void* src) {
    asm volatile("cp.async.cg.shared.global [%0], [%1], 16;" :: "r"(dst), "l"(src));
}
#define CP_COMMIT asm volatile("cp.async.commit_group;" ::: "memory")
#define CP_WAIT1  asm volatile("cp.async.wait_group 1;" ::: "memory")
#define CP_WAIT2  asm volatile("cp.async.wait_group 2;" ::: "memory")

// f32 -> f16 conversion pass (8 elems per thread-step)
__global__ void __launch_bounds__(256) cvt_h(__half* __restrict__ d, const float* __restrict__ s, int n8) {
    int i = blockIdx.x * blockDim.x + threadIdx.x, st = gridDim.x * blockDim.x;
    const float4* s4 = (const float4*)s;
    uint4* d4 = (uint4*)d;
    for (; i < n8; i += st) {
        float4 v0 = s4[2 * i], v1 = s4[2 * i + 1];
        __half2 h0 = __floats2half2_rn(v0.x, v0.y);
        __half2 h1 = __floats2half2_rn(v0.z, v0.w);
        __half2 h2 = __floats2half2_rn(v1.x, v1.y);
        __half2 h3 = __floats2half2_rn(v1.z, v1.w);
        uint4 o;
        o.x = *(uint32_t*)&h0; o.y = *(uint32_t*)&h1;
        o.z = *(uint32_t*)&h2; o.w = *(uint32_t*)&h3;
        d4[i] = o;
    }
}

// half GEMM: C[m,n] = sum_k A[m,k]*B[n,k] (+bias[n]); A,B K-major half, K=4096.
// 128x128 tile, 4 warps of 64x64, BK=32 (2 x k16 chunks), 4-stage cp.async,
// cross-barrier register double-buffering.
#define RSH 40                          // smem row stride in halves (32 + 8 pad)
#define STGB (128 * RSH * 2 * 2)        // stage bytes (A+B)
#define NSTG 4

#define LOADF(Asp, Bsp, KH, aa, bb) do {                                        \
    _Pragma("unroll") for (int mt = 0; mt < 4; mt++) {                          \
        aa[mt][0] = *(const uint32_t*)((Asp) + mt * 16 * RSH + (KH));           \
        aa[mt][1] = *(const uint32_t*)((Asp) + (mt * 16 + 8) * RSH + (KH));     \
        aa[mt][2] = *(const uint32_t*)((Asp) + mt * 16 * RSH + (KH) + 8);       \
        aa[mt][3] = *(const uint32_t*)((Asp) + (mt * 16 + 8) * RSH + (KH) + 8); \
    }                                                                           \
    _Pragma("unroll") for (int nt = 0; nt < 8; nt++) {                          \
        bb[nt][0] = *(const uint32_t*)((Bsp) + nt * 8 * RSH + (KH));            \
        bb[nt][1] = *(const uint32_t*)((Bsp) + nt * 8 * RSH + (KH) + 8);        \
    }                                                                           \
} while (0)

#define MMAS(aa, bb) do {                                                       \
    _Pragma("unroll") for (int mt = 0; mt < 4; mt++)                            \
        _Pragma("unroll") for (int nt = 0; nt < 8; nt++)                        \
            mma16(acc[mt][nt], aa[mt], bb[nt]);                                 \
} while (0)

__global__ void __launch_bounds__(128, 2) gemm_f16(
    const __half* __restrict__ A, const __half* __restrict__ B,
    float* __restrict__ C, const float* __restrict__ bias, int ntot)
{
    extern __shared__ __align__(16) __half smh[];
    const int tid = threadIdx.x, lane = tid & 31, wid = tid >> 5;
    const int gid = lane >> 2, tig = lane & 3;
    const int wm = wid & 1, wn = wid >> 1;          // 2x2 warp grid, 64x64 each

    const int tn = gridDim.x, tm = gridDim.y;
    const int lin = blockIdx.y * tn + blockIdx.x;
    const int GN = 8;
    const int stripe = lin / (tm * GN), rem = lin - stripe * (tm * GN);
    const int width = min(GN, tn - stripe * GN);
    const int n0 = (stripe * GN + rem % width) * 128;
    const int m0 = (rem / width) * 128;

    float acc[4][8][4] = {};
    const uint32_t sb = smem_u32(smh);

    auto issue = [&](int sidx, int kt) {
        uint32_t da = sb + sidx * STGB, db = da + 128 * RSH * 2;
        #pragma unroll
        for (int i = tid; i < 512; i += 128) {
            int r = i >> 2, c = i & 3;
            cpasync16(da + r * RSH * 2 + c * 16, A + (size_t)(m0 + r) * 4096 + kt * 32 + c * 8);
            cpasync16(db + r * RSH * 2 + c * 16, B + (size_t)(n0 + r) * 4096 + kt * 32 + c * 8);
        }
    };

    issue(0, 0); CP_COMMIT;
    issue(1, 1); CP_COMMIT;
    issue(2, 2); CP_COMMIT;

    const int aoff = (wm * 64 + gid) * RSH;
    const int boff = 128 * RSH + (wn * 64 + gid) * RSH;
    const int kh0 = tig * 2, kh1 = 16 + tig * 2;    // two k16 chunks in BK=32

    uint32_t a0[4][4], b0[8][2], a1[4][4], b1[8][2];

    CP_WAIT2;
    __syncthreads();
    LOADF(smh + aoff, smh + boff, kh0, a0, b0);

    int buf = 0;
    #pragma unroll 1
    for (int kt = 0; kt < 128; kt++) {
        CP_WAIT1;               // stages kt and kt+1 complete
        __syncthreads();
        int nb = buf + 3; if (nb >= NSTG) nb -= NSTG;
        if (kt + 3 < 128) issue(nb, kt + 3);
        CP_COMMIT;

        const __half* As = smh + buf * (STGB / 2);
        int buf1 = buf + 1; if (buf1 >= NSTG) buf1 -= NSTG;
        const __half* As1 = smh + buf1 * (STGB / 2);

        LOADF(As + aoff, As + boff, kh1, a1, b1);        // this tile, chunk 1
        MMAS(a0, b0);                                    // chunk 0
        if (kt + 1 < 128)
            LOADF(As1 + aoff, As1 + boff, kh0, a0, b0);  // next tile, chunk 0
        MMAS(a1, b1);                                    // chunk 1

        buf = buf1;
    }

    #pragma unroll
    for (int mt = 0; mt < 4; mt++) {
        #pragma unroll
        for (int nt = 0; nt < 8; nt++) {
            int row = m0 + wm * 64 + mt * 16 + gid;
            int col = n0 + wn * 64 + nt * 8 + tig * 2;
            float b0v = 0.f, b1v = 0.f;
            if (bias) { b0v = bias[col]; b1v = bias[col + 1]; }
            *(float2*)(C + (size_t)row * ntot + col) =
                make_float2(acc[mt][nt][0] + b0v, acc[mt][nt][1] + b1v);
            *(float2*)(C + (size_t)(row + 8) * ntot + col) =
                make_float2(acc[mt][nt][2] + b0v, acc[mt][nt][3] + b1v);
        }
    }
}

// per-token 32x32 head-mixing attention; qkv f32 in, out half, col = d*32+h
#define RS 132
__global__ void __launch_bounds__(128) attn_kernel(
    const float* __restrict__ qkv, __half* __restrict__ attn)
{
    extern __shared__ float sm[];
    const int b = blockIdx.x, t = threadIdx.x, w = t >> 5, lane = t & 31;

    const float4* src4 = (const float4*)(qkv + (size_t)b * NQKV);
    for (int i = t; i < 3072; i += 128) {
        int mat = i >> 10, rm = i & 1023;
        *(float4*)(sm + mat * (32 * RS) + (rm >> 5) * RS + (rm & 31) * 4) = src4[i];
    }
    __syncthreads();

    float* sq = sm;
    float* sk = sm + 32 * RS;
    float* sv = sm + 64 * RS;
    float* ss = sm + 96 * RS;
    const float scale = 0.08838834764831845f;

    {
        float a8[8] = {};
        #pragma unroll
        for (int ch = 0; ch < 4; ch++) {
            float4 q[8];
            #pragma unroll
            for (int j = 0; j < 8; j++)
                q[j] = *(const float4*)(sq + lane * RS + ch * 32 + j * 4);
            #pragma unroll
            for (int g0 = 0; g0 < 8; g0++) {
                const float* kr = sk + (w * 8 + g0) * RS + ch * 32;
                #pragma unroll
                for (int j = 0; j < 8; j++) {
                    float4 k4 = *(const float4*)(kr + j * 4);
                    a8[g0] += q[j].x * k4.x + q[j].y * k4.y + q[j].z * k4.z + q[j].w * k4.w;
                }
            }
        }
        #pragma unroll
        for (int g0 = 0; g0 < 8; g0++) ss[lane * 33 + w * 8 + g0] = a8[g0] * scale;
    }
    __syncthreads();

    if (w == 0) {
        float mx = -1e30f;
        #pragma unroll
        for (int g = 0; g < 32; g++) mx = fmaxf(mx, ss[lane * 33 + g]);
        float sum = 0.f;
        #pragma unroll
        for (int g = 0; g < 32; g++) {
            float e = __expf(ss[lane * 33 + g] - mx);
            ss[lane * 33 + g] = e; sum += e;
        }
        float inv = 1.f / sum;
        #pragma unroll
        for (int g = 0; g < 32; g++) ss[lane * 33 + g] *= inv;
    }
    __syncthreads();

    {
        float4 acc[8];
        #pragma unroll
        for (int j = 0; j < 8; j++) acc[j] = make_float4(0.f, 0.f, 0.f, 0.f);
        #pragma unroll
        for (int g = 0; g < 32; g++) {
            float a = ss[lane * 33 + g];
            const float* vr = sv + g * RS + w * 32;
            #pragma unroll
            for (int j = 0; j < 8; j++) {
                float4 v4 = *(const float4*)(vr + j * 4);
                acc[j].x += a * v4.x; acc[j].y += a * v4.y;
                acc[j].z += a * v4.z; acc[j].w += a * v4.w;
            }
        }
        __half* dst = attn + (size_t)b * CDIM;
        #pragma unroll
        for (int j = 0; j < 8; j++) {
            int d0 = w * 32 + j * 4;
            dst[(d0 + 0) * 32 + lane] = __float2half_rn(acc[j].x);
            dst[(d0 + 1) * 32 + lane] = __float2half_rn(acc[j].y);
            dst[(d0 + 2) * 32 + lane] = __float2half_rn(acc[j].z);
            dst[(d0 + 3) * 32 + lane] = __float2half_rn(acc[j].w);
        }
    }
}

extern "C" void kernel_launch(void* const* d_in, const int* in_sizes, int n_in,
                              void* d_out, int out_size)
{
    const float* x  = (const float*)d_in[0];
    const float* wq = (const float*)d_in[1];
    const float* wp = (const float*)d_in[2];
    const float* bp = (const float*)d_in[3];
    float* out = (float*)d_out;

    __half *hx, *hwq, *hwp, *hattn;
    float *qkv;
    cudaGetSymbolAddress((void**)&hx, h_x);
    cudaGetSymbolAddress((void**)&hwq, h_wq);
    cudaGetSymbolAddress((void**)&hwp, h_wp);
    cudaGetSymbolAddress((void**)&qkv, g_qkv);
    cudaGetSymbolAddress((void**)&hattn, h_attn);

    cudaFuncSetAttribute(gemm_f16, cudaFuncAttributeMaxDynamicSharedMemorySize, NSTG * STGB);
    cudaFuncSetAttribute(attn_kernel, cudaFuncAttributeMaxDynamicSharedMemorySize, 55296);

    cvt_h<<<512, 256>>>(hx, x, (int)((size_t)BDIM * CDIM / 8));
    cvt_h<<<512, 256>>>(hwq, wq, (int)((size_t)NQKV * CDIM / 8));
    cvt_h<<<512, 256>>>(hwp, wp, (int)((size_t)CDIM * CDIM / 8));
    gemm_f16<<<dim3(96, 64), 128, NSTG * STGB>>>(hx, hwq, qkv, nullptr, NQKV);
    attn_kernel<<<BDIM, 128, 55296>>>(qkv, hattn);
    gemm_f16<<<dim3(32, 64), 128, NSTG * STGB>>>(hattn, hwp, out, bp, CDIM);
}